// round 3
// baseline (speedup 1.0000x reference)
#include <cuda_runtime.h>
#include <math.h>

// Bahdanau additive attention, fp32 baseline.
//   enc_out:    [B=32, T=2048, H=1024]  d_in[0]
//   dec_hidden: [B, H]                   d_in[1]
//   Wa:         [H, U=1024]              d_in[2]
//   Ua:         [H, U]                   d_in[3]
//   Va:         [U]                      d_in[4]
//   out:        context [B, H] fp32
//
// Pipeline: K0 zero out -> K1 dec_proj -> K2 fused score GEMM (enc@Ua,
// +bias, tanh, dot Va) -> K3 softmax -> K4 context (alpha-weighted sum).

#define BATCH 32
#define TSEQ  2048
#define HDIM  1024
#define UDIM  1024
#define BT    (BATCH * TSEQ)

#define BM 64
#define BN 64
#define BK 16

// scratch (no allocations allowed -> __device__ globals)
__device__ float g_score[BT];           // score, then alpha in-place
__device__ float g_decproj[BATCH * UDIM];

// ---------------------------------------------------------------- K0: zero out
__global__ void k0_zero(float* out, int n) {
    int i = blockIdx.x * blockDim.x + threadIdx.x;
    if (i < n) out[i] = 0.0f;
}

// ------------------------------------------------- K1: dec_proj = dec_hidden@Wa
// grid (UDIM/256, BATCH), 256 threads
__global__ void k1_decproj(const float* __restrict__ dec,
                           const float* __restrict__ Wa) {
    __shared__ float dh[HDIM];
    int b = blockIdx.y;
    for (int h = threadIdx.x; h < HDIM; h += 256)
        dh[h] = dec[b * HDIM + h];
    __syncthreads();
    int u = blockIdx.x * 256 + threadIdx.x;
    float acc = 0.0f;
    #pragma unroll 8
    for (int h = 0; h < HDIM; h++)
        acc = fmaf(dh[h], Wa[(size_t)h * UDIM + u], acc);
    g_decproj[b * UDIM + u] = acc;
}

// -------------------------- K2: fused score = Va . tanh(enc@Ua + dec_proj[b])
// grid (BT/BM) blocks of 256 threads. Each block: BM rows of the flattened
// [B*T, H] enc matrix; loops U in BN tiles, K in BK tiles; 4x4 register tile
// per thread; epilogue reduces over the BN columns with tanh*Va into
// per-row score accumulators in smem (never materializes [B,T,U]).
__global__ __launch_bounds__(256, 4) void k2_score(
    const float* __restrict__ enc,
    const float* __restrict__ Ua,
    const float* __restrict__ Va) {

    __shared__ float As[BK][BM];       // transposed A tile
    __shared__ float Bs[BK][BN];
    __shared__ float bias_s[BN];
    __shared__ float va_s[BN];
    __shared__ float score_s[BM];

    const int tid = threadIdx.x;
    const int tx = tid & 15;           // 0..15 -> 4 cols each
    const int ty = tid >> 4;           // 0..15 -> 4 rows each
    const int row0 = blockIdx.x * BM;
    const int b = row0 / TSEQ;         // BM=64 divides TSEQ -> single b per block
    const float* Arow = enc + (size_t)row0 * HDIM;

    if (tid < BM) score_s[tid] = 0.0f;

    // A tile load mapping: thread -> (row, 4 consecutive k)
    const int la_row = tid >> 2;           // 0..63
    const int la_k4  = (tid & 3) * 4;      // 0,4,8,12
    // B tile load mapping: thread -> (k, 4 consecutive u)
    const int lb_k  = tid >> 4;            // 0..15
    const int lb_u4 = (tid & 15) * 4;      // 0..60

    for (int nt = 0; nt < UDIM / BN; nt++) {
        const int u0 = nt * BN;
        __syncthreads();   // prior epilogue's bias/score reads complete
        if (tid < BN) {
            bias_s[tid] = g_decproj[b * UDIM + u0 + tid];
            va_s[tid]   = Va[u0 + tid];
        }

        float acc[4][4] = {};

        for (int kt = 0; kt < HDIM / BK; kt++) {
            const int k0 = kt * BK;
            __syncthreads();  // previous tile fully consumed
            float4 av = *(const float4*)(Arow + (size_t)la_row * HDIM + k0 + la_k4);
            As[la_k4 + 0][la_row] = av.x;
            As[la_k4 + 1][la_row] = av.y;
            As[la_k4 + 2][la_row] = av.z;
            As[la_k4 + 3][la_row] = av.w;
            float4 bv = *(const float4*)(Ua + (size_t)(k0 + lb_k) * UDIM + u0 + lb_u4);
            *(float4*)&Bs[lb_k][lb_u4] = bv;
            __syncthreads();

            #pragma unroll
            for (int k = 0; k < BK; k++) {
                float4 a4 = *(const float4*)&As[k][ty * 4];
                float4 b4 = *(const float4*)&Bs[k][tx * 4];
                float ar[4] = {a4.x, a4.y, a4.z, a4.w};
                float br[4] = {b4.x, b4.y, b4.z, b4.w};
                #pragma unroll
                for (int i = 0; i < 4; i++)
                    #pragma unroll
                    for (int j = 0; j < 4; j++)
                        acc[i][j] = fmaf(ar[i], br[j], acc[i][j]);
            }
        }

        // epilogue: tanh + Va reduction over this BN slab
        #pragma unroll
        for (int i = 0; i < 4; i++) {
            float s = 0.0f;
            #pragma unroll
            for (int j = 0; j < 4; j++) {
                float v = tanhf(acc[i][j] + bias_s[tx * 4 + j]);
                s = fmaf(va_s[tx * 4 + j], v, s);
            }
            atomicAdd(&score_s[ty * 4 + i], s);
        }
    }

    __syncthreads();
    if (tid < BM) g_score[row0 + tid] = score_s[tid];
}

// ---------------------------------------------- K3: softmax over T (in place)
__global__ void k3_softmax() {
    __shared__ float red[256];
    const int b = blockIdx.x;
    const int tid = threadIdx.x;
    float* row = g_score + (size_t)b * TSEQ;

    float m = -1e30f;
    for (int t = tid; t < TSEQ; t += 256) m = fmaxf(m, row[t]);
    red[tid] = m; __syncthreads();
    for (int s = 128; s > 0; s >>= 1) {
        if (tid < s) red[tid] = fmaxf(red[tid], red[tid + s]);
        __syncthreads();
    }
    m = red[0];
    __syncthreads();

    float sum = 0.0f;
    for (int t = tid; t < TSEQ; t += 256) {
        float e = __expf(row[t] - m);
        row[t] = e;
        sum += e;
    }
    red[tid] = sum; __syncthreads();
    for (int s = 128; s > 0; s >>= 1) {
        if (tid < s) red[tid] += red[tid + s];
        __syncthreads();
    }
    float inv = 1.0f / red[0];
    __syncthreads();
    for (int t = tid; t < TSEQ; t += 256) row[t] *= inv;
}

// --------------------------------- K4: context[b,h] = sum_t alpha[b,t]*enc[b,t,h]
// grid (TSEQ/128, BATCH), 256 threads; each thread owns 4 h (float4),
// accumulates over a 128-t chunk, atomically adds into out.
__global__ void k4_context(const float* __restrict__ enc, float* __restrict__ out) {
    __shared__ float al[128];
    const int b = blockIdx.y;
    const int t0 = blockIdx.x * 128;
    const int tid = threadIdx.x;
    if (tid < 128) al[tid] = g_score[(size_t)b * TSEQ + t0 + tid];
    __syncthreads();

    float4 acc = make_float4(0.f, 0.f, 0.f, 0.f);
    const float* base = enc + ((size_t)b * TSEQ + t0) * HDIM + tid * 4;
    #pragma unroll 4
    for (int tt = 0; tt < 128; tt++) {
        float a = al[tt];
        float4 e = *(const float4*)(base + (size_t)tt * HDIM);
        acc.x = fmaf(a, e.x, acc.x);
        acc.y = fmaf(a, e.y, acc.y);
        acc.z = fmaf(a, e.z, acc.z);
        acc.w = fmaf(a, e.w, acc.w);
    }
    float* o = out + (size_t)b * HDIM + tid * 4;
    atomicAdd(o + 0, acc.x);
    atomicAdd(o + 1, acc.y);
    atomicAdd(o + 2, acc.z);
    atomicAdd(o + 3, acc.w);
}

// ------------------------------------------------------------------- launcher
extern "C" void kernel_launch(void* const* d_in, const int* in_sizes, int n_in,
                              void* d_out, int out_size) {
    const float* enc = (const float*)d_in[0];  // [B,T,H]
    const float* dec = (const float*)d_in[1];  // [B,H]
    const float* Wa  = (const float*)d_in[2];  // [H,U]
    const float* Ua  = (const float*)d_in[3];  // [H,U]
    const float* Va  = (const float*)d_in[4];  // [U]
    float* out = (float*)d_out;                // [B,H]

    (void)in_sizes; (void)n_in; (void)out_size;

    k0_zero<<<(BATCH * HDIM + 255) / 256, 256>>>(out, BATCH * HDIM);
    k1_decproj<<<dim3(UDIM / 256, BATCH), 256>>>(dec, Wa);
    k2_score<<<BT / BM, 256>>>(enc, Ua, Va);
    k3_softmax<<<BATCH, 256>>>();
    k4_context<<<dim3(TSEQ / 128, BATCH), 256>>>(enc, out);
}

// round 7
// speedup vs baseline: 3.2504x; 3.2504x over previous
#include <cuda_runtime.h>
#include <cuda_bf16.h>
#include <cstdint>
#include <math.h>

// Bahdanau additive attention on GB300 (sm_103a, but harness emits BASE
// compute_103 PTX -> no tcgen05; use mma.sync HMMA bf16 instead).
//   enc_out:    [B=32, T=2048, H=1024]  d_in[0]  fp32
//   dec_hidden: [B, H]                   d_in[1]
//   Wa:         [H, U=1024]              d_in[2]
//   Ua:         [H, U]                   d_in[3]
//   Va:         [U]                      d_in[4]
//   out: context [B, H] fp32
//
// Score GEMM: split-bf16 (Ahi*Bhi + Ahi*Blo + Alo*Bhi, fp32 accum) via
// mma.sync.m16n8k16, cp.async double-buffered smem tiles, fused
// bias+tanh+Va epilogue.

#define BATCH 32
#define TSEQ  2048
#define HDIM  1024
#define UDIM  1024
#define BT    (BATCH * TSEQ)

// ---------------------------------------------------------------- scratch
__device__ float g_score[BT];
__device__ float g_decproj[BATCH * UDIM];
__device__ __nv_bfloat16 g_enc_hi[(size_t)BT * HDIM];
__device__ __nv_bfloat16 g_enc_lo[(size_t)BT * HDIM];
__device__ __nv_bfloat16 g_ua_hi[(size_t)UDIM * HDIM];  // transposed [U][H]
__device__ __nv_bfloat16 g_ua_lo[(size_t)UDIM * HDIM];

// ---------------------------------------------------------------- helpers
__device__ __forceinline__ uint32_t smem_u32(const void* p) {
    uint32_t a;
    asm("{ .reg .u64 t; cvta.to.shared.u64 t, %1; cvt.u32.u64 %0, t; }"
        : "=r"(a) : "l"(p));
    return a;
}
__device__ __forceinline__ uint32_t swz(uint32_t off) {
    return off ^ ((off >> 3) & 0x70);   // SW128 on 128B rows
}
__device__ __forceinline__ void cp16(uint32_t dst, const void* src) {
    asm volatile("cp.async.cg.shared.global [%0], [%1], 16;"
                 :: "r"(dst), "l"(src));
}
#define CP_COMMIT() asm volatile("cp.async.commit_group;" ::: "memory")
#define CP_WAIT1()  asm volatile("cp.async.wait_group 1;" ::: "memory")
#define CP_WAIT0()  asm volatile("cp.async.wait_group 0;" ::: "memory")

__device__ __forceinline__ void ldm4(uint32_t& r0, uint32_t& r1,
                                     uint32_t& r2, uint32_t& r3, uint32_t a) {
    asm volatile("ldmatrix.sync.aligned.m8n8.x4.shared.b16 {%0,%1,%2,%3}, [%4];"
                 : "=r"(r0), "=r"(r1), "=r"(r2), "=r"(r3) : "r"(a));
}
__device__ __forceinline__ void mma16816(float* c, const uint32_t* a,
                                         const uint32_t* b) {
    asm volatile(
        "mma.sync.aligned.m16n8k16.row.col.f32.bf16.bf16.f32 "
        "{%0,%1,%2,%3}, {%4,%5,%6,%7}, {%8,%9}, {%0,%1,%2,%3};"
        : "+f"(c[0]), "+f"(c[1]), "+f"(c[2]), "+f"(c[3])
        : "r"(a[0]), "r"(a[1]), "r"(a[2]), "r"(a[3]), "r"(b[0]), "r"(b[1]));
}

__device__ __forceinline__ void split2(float x, __nv_bfloat16& hi, __nv_bfloat16& lo) {
    __nv_bfloat16 h = __float2bfloat16(x);
    hi = h;
    lo = __float2bfloat16(x - __bfloat162float(h));
}

// -------------------------------------------- P1: enc -> bf16 hi/lo (vec4)
__global__ void p_split_enc(const float* __restrict__ enc) {
    size_t i = (size_t)blockIdx.x * blockDim.x + threadIdx.x;
    float4 v = ((const float4*)enc)[i];
    __nv_bfloat16 h0, h1, h2, h3, l0, l1, l2, l3;
    split2(v.x, h0, l0); split2(v.y, h1, l1);
    split2(v.z, h2, l2); split2(v.w, h3, l3);
    ushort4 hv, lv;
    hv.x = __bfloat16_as_ushort(h0); hv.y = __bfloat16_as_ushort(h1);
    hv.z = __bfloat16_as_ushort(h2); hv.w = __bfloat16_as_ushort(h3);
    lv.x = __bfloat16_as_ushort(l0); lv.y = __bfloat16_as_ushort(l1);
    lv.z = __bfloat16_as_ushort(l2); lv.w = __bfloat16_as_ushort(l3);
    ((ushort4*)g_enc_hi)[i] = hv;
    ((ushort4*)g_enc_lo)[i] = lv;
}

// ------------------------------- P2: Ua [H,U] -> transposed [U,H] bf16 hi/lo
__global__ void p_trans_ua(const float* __restrict__ Ua) {
    __shared__ float tile[32][33];
    int tx = threadIdx.x, ty = threadIdx.y;  // (32, 8)
    int u0 = blockIdx.x * 32, h0 = blockIdx.y * 32;
    #pragma unroll
    for (int j = 0; j < 4; j++)
        tile[ty + 8 * j][tx] = Ua[(size_t)(h0 + ty + 8 * j) * UDIM + u0 + tx];
    __syncthreads();
    #pragma unroll
    for (int j = 0; j < 4; j++) {
        float v = tile[tx][ty + 8 * j];
        __nv_bfloat16 hi, lo;
        split2(v, hi, lo);
        size_t o = (size_t)(u0 + ty + 8 * j) * HDIM + h0 + tx;
        g_ua_hi[o] = hi;
        g_ua_lo[o] = lo;
    }
}

// ---------------------------------------------------------------- K0: zero
__global__ void k0_zero(float* out, int n) {
    int i = blockIdx.x * blockDim.x + threadIdx.x;
    if (i < n) out[i] = 0.0f;
}

// --------------------------------------------- K1: dec_proj = dec_hidden@Wa
__global__ void k1_decproj(const float* __restrict__ dec,
                           const float* __restrict__ Wa) {
    __shared__ float dh[HDIM];
    int b = blockIdx.y;
    for (int h = threadIdx.x; h < HDIM; h += 256)
        dh[h] = dec[b * HDIM + h];
    __syncthreads();
    int u = blockIdx.x * 256 + threadIdx.x;
    float acc = 0.0f;
    #pragma unroll 8
    for (int h = 0; h < HDIM; h++)
        acc = fmaf(dh[h], Wa[(size_t)h * UDIM + u], acc);
    g_decproj[b * UDIM + u] = acc;
}

// ------------------- K2: fused score via split-bf16 HMMA GEMM + epilogue
// grid 512 CTAs x 256 threads. CTA tile M=128 x N=128, K-chunk 64,
// 2-stage cp.async pipeline. Warp grid 4(m) x 2(n); warp tile m32 x n64.
#define K2_M   128
#define K2_N   128
#define K2_KC  64
#define NT_CNT (UDIM / K2_N)     // 8
#define KT_CNT (HDIM / K2_KC)    // 16
#define IT_TOT (NT_CNT * KT_CNT) // 128

#define TILE_B   (128 * 128)     // one [128 rows][64 bf16] tile = 16 KB
#define OFF_AHI  0
#define OFF_ALO  (TILE_B)
#define OFF_BHI  (2 * TILE_B)
#define OFF_BLO  (3 * TILE_B)
#define STAGE_B  (4 * TILE_B)    // 64 KB
#define SM_BIAS  (2 * STAGE_B)           // after both stages
#define SM_VA    (SM_BIAS + K2_N * 4)
#define SM_SCORE (SM_VA + K2_N * 4)
#define SM_TOTAL (SM_SCORE + K2_M * 4)   // 132 KB

__device__ __forceinline__ void issue_chunk(uint32_t sb, int stage, int row0,
                                            int it, int tid) {
    const int nt = it >> 4, kt = it & 15;
    const int u0 = nt * K2_N;
    const int kg = kt * K2_KC;
    const uint32_t base = sb + stage * STAGE_B;
    #pragma unroll
    for (int i = 0; i < 4; i++) {
        int s = tid + i * 256;        // 0..1023
        int r = s >> 3, seg = s & 7;  // row, 16B segment
        uint32_t so = swz((uint32_t)(r * 128 + seg * 16));
        size_t ao = (size_t)(row0 + r) * HDIM + kg + seg * 8;
        size_t bo = (size_t)(u0 + r) * HDIM + kg + seg * 8;
        cp16(base + OFF_AHI + so, g_enc_hi + ao);
        cp16(base + OFF_ALO + so, g_enc_lo + ao);
        cp16(base + OFF_BHI + so, g_ua_hi + bo);
        cp16(base + OFF_BLO + so, g_ua_lo + bo);
    }
}

__global__ void __launch_bounds__(256, 1)
k2_score(const float* __restrict__ Va) {
    extern __shared__ char smem[];
    const uint32_t sb = smem_u32(smem);
    const int tid = threadIdx.x;
    const int lane = tid & 31;
    const int wid = tid >> 5;
    const int warp_m = wid >> 1;          // 0..3 -> m offset *32
    const int warp_n = wid & 1;           // 0..1 -> n offset *64
    const int row0 = blockIdx.x * K2_M;
    const int b = row0 / TSEQ;

    float* bias_s  = (float*)(smem + SM_BIAS);
    float* va_s    = (float*)(smem + SM_VA);
    float* score_s = (float*)(smem + SM_SCORE);
    if (tid < K2_M) score_s[tid] = 0.0f;

    // prologue: chunk 0 -> stage 0
    issue_chunk(sb, 0, row0, 0, tid);
    CP_COMMIT();

    float c[2][8][4];

    for (int it = 0; it < IT_TOT; it++) {
        const int nt = it >> 4, kt = it & 15;
        const int stage = it & 1;

        if (it + 1 < IT_TOT) {
            issue_chunk(sb, stage ^ 1, row0, it + 1, tid);
            CP_COMMIT();
            CP_WAIT1();
        } else {
            CP_WAIT0();
        }
        __syncthreads();

        if (kt == 0) {
            if (tid < K2_N) {
                bias_s[tid] = g_decproj[b * UDIM + nt * K2_N + tid];
                va_s[tid]   = Va[nt * K2_N + tid];
            }
            #pragma unroll
            for (int mi = 0; mi < 2; mi++)
                #pragma unroll
                for (int ni = 0; ni < 8; ni++)
                    #pragma unroll
                    for (int q = 0; q < 4; q++)
                        c[mi][ni][q] = 0.0f;
        }

        // ---- compute this chunk (4 x k16 steps)
        const uint32_t aHi = sb + stage * STAGE_B + OFF_AHI;
        const uint32_t aLo = sb + stage * STAGE_B + OFF_ALO;
        const uint32_t bHi = sb + stage * STAGE_B + OFF_BHI;
        const uint32_t bLo = sb + stage * STAGE_B + OFF_BLO;

        #pragma unroll
        for (int ks = 0; ks < 4; ks++) {
            const int kb = ks * 32;  // byte offset of k16 step
            uint32_t ahi[2][4], alo[2][4];
            #pragma unroll
            for (int mi = 0; mi < 2; mi++) {
                uint32_t ar = warp_m * 32 + mi * 16 + (lane & 15);
                uint32_t off = swz(ar * 128 + kb + (lane >> 4) * 16);
                ldm4(ahi[mi][0], ahi[mi][1], ahi[mi][2], ahi[mi][3], aHi + off);
                ldm4(alo[mi][0], alo[mi][1], alo[mi][2], alo[mi][3], aLo + off);
            }
            uint32_t bhi[8][2], blo[8][2];
            #pragma unroll
            for (int np = 0; np < 4; np++) {   // each covers 2 n8 tiles
                uint32_t nr = warp_n * 64 + np * 16 + (lane & 7) +
                              ((lane >> 4) ? 8u : 0u);
                uint32_t off = swz(nr * 128 + kb + ((lane >> 3) & 1) * 16);
                uint32_t r0, r1, r2, r3;
                ldm4(r0, r1, r2, r3, bHi + off);
                bhi[np * 2][0] = r0; bhi[np * 2][1] = r1;
                bhi[np * 2 + 1][0] = r2; bhi[np * 2 + 1][1] = r3;
                ldm4(r0, r1, r2, r3, bLo + off);
                blo[np * 2][0] = r0; blo[np * 2][1] = r1;
                blo[np * 2 + 1][0] = r2; blo[np * 2 + 1][1] = r3;
            }
            #pragma unroll
            for (int mi = 0; mi < 2; mi++)
                #pragma unroll
                for (int ni = 0; ni < 8; ni++) {
                    mma16816(c[mi][ni], ahi[mi], bhi[ni]);
                    mma16816(c[mi][ni], ahi[mi], blo[ni]);
                    mma16816(c[mi][ni], alo[mi], bhi[ni]);
                }
        }

        // ---- epilogue at end of each N-slab
        if (kt == KT_CNT - 1) {
            const int qc = lane & 3;
            const int gl = lane >> 2;
            #pragma unroll
            for (int mi = 0; mi < 2; mi++) {
                float s0 = 0.0f, s1 = 0.0f;  // rows r and r+8
                #pragma unroll
                for (int ni = 0; ni < 8; ni++) {
                    int col = warp_n * 64 + ni * 8 + qc * 2;
                    float b0 = bias_s[col], b1 = bias_s[col + 1];
                    float v0 = va_s[col],  v1 = va_s[col + 1];
                    s0 = fmaf(v0, tanhf(c[mi][ni][0] + b0), s0);
                    s0 = fmaf(v1, tanhf(c[mi][ni][1] + b1), s0);
                    s1 = fmaf(v0, tanhf(c[mi][ni][2] + b0), s1);
                    s1 = fmaf(v1, tanhf(c[mi][ni][3] + b1), s1);
                }
                s0 += __shfl_xor_sync(0xFFFFFFFF, s0, 1);
                s0 += __shfl_xor_sync(0xFFFFFFFF, s0, 2);
                s1 += __shfl_xor_sync(0xFFFFFFFF, s1, 1);
                s1 += __shfl_xor_sync(0xFFFFFFFF, s1, 2);
                if (qc == 0) {
                    int r = warp_m * 32 + mi * 16 + gl;
                    atomicAdd(&score_s[r], s0);
                    atomicAdd(&score_s[r + 8], s1);
                }
            }
        }
        __syncthreads();   // stage fully consumed before reuse; bias stable
    }

    if (tid < K2_M) g_score[row0 + tid] = score_s[tid];
}

// ---------------------------------------------- K3: softmax over T (in place)
__global__ void k3_softmax() {
    __shared__ float red[256];
    const int b = blockIdx.x;
    const int tid = threadIdx.x;
    float* row = g_score + (size_t)b * TSEQ;

    float m = -1e30f;
    for (int t = tid; t < TSEQ; t += 256) m = fmaxf(m, row[t]);
    red[tid] = m; __syncthreads();
    for (int s = 128; s > 0; s >>= 1) {
        if (tid < s) red[tid] = fmaxf(red[tid], red[tid + s]);
        __syncthreads();
    }
    m = red[0];
    __syncthreads();

    float sum = 0.0f;
    for (int t = tid; t < TSEQ; t += 256) {
        float e = __expf(row[t] - m);
        row[t] = e;
        sum += e;
    }
    red[tid] = sum; __syncthreads();
    for (int s = 128; s > 0; s >>= 1) {
        if (tid < s) red[tid] += red[tid + s];
        __syncthreads();
    }
    float inv = 1.0f / red[0];
    __syncthreads();
    for (int t = tid; t < TSEQ; t += 256) row[t] *= inv;
}

// ------------------------- K4: context[b,h] = sum_t alpha[b,t]*enc[b,t,h]
__global__ void k4_context(const float* __restrict__ enc, float* __restrict__ out) {
    __shared__ float al[128];
    const int b = blockIdx.y;
    const int t0 = blockIdx.x * 128;
    const int tid = threadIdx.x;
    if (tid < 128) al[tid] = g_score[(size_t)b * TSEQ + t0 + tid];
    __syncthreads();

    float4 acc = make_float4(0.f, 0.f, 0.f, 0.f);
    const float* base = enc + ((size_t)b * TSEQ + t0) * HDIM + tid * 4;
    #pragma unroll 4
    for (int tt = 0; tt < 128; tt++) {
        float a = al[tt];
        float4 e = *(const float4*)(base + (size_t)tt * HDIM);
        acc.x = fmaf(a, e.x, acc.x);
        acc.y = fmaf(a, e.y, acc.y);
        acc.z = fmaf(a, e.z, acc.z);
        acc.w = fmaf(a, e.w, acc.w);
    }
    float* o = out + (size_t)b * HDIM + tid * 4;
    atomicAdd(o + 0, acc.x);
    atomicAdd(o + 1, acc.y);
    atomicAdd(o + 2, acc.z);
    atomicAdd(o + 3, acc.w);
}

// ------------------------------------------------------------------- launcher
extern "C" void kernel_launch(void* const* d_in, const int* in_sizes, int n_in,
                              void* d_out, int out_size) {
    const float* enc = (const float*)d_in[0];
    const float* dec = (const float*)d_in[1];
    const float* Wa  = (const float*)d_in[2];
    const float* Ua  = (const float*)d_in[3];
    const float* Va  = (const float*)d_in[4];
    float* out = (float*)d_out;
    (void)in_sizes; (void)n_in; (void)out_size;

    cudaFuncSetAttribute(k2_score, cudaFuncAttributeMaxDynamicSharedMemorySize,
                         SM_TOTAL);

    k0_zero<<<(BATCH * HDIM + 255) / 256, 256>>>(out, BATCH * HDIM);
    p_split_enc<<<(BT * HDIM / 4) / 256, 256>>>(enc);
    p_trans_ua<<<dim3(UDIM / 32, HDIM / 32), dim3(32, 8)>>>(Ua);
    k1_decproj<<<dim3(UDIM / 256, BATCH), 256>>>(dec, Wa);
    k2_score<<<BT / K2_M, 256, SM_TOTAL>>>(Va);
    k3_softmax<<<BATCH, 256>>>();
    k4_context<<<dim3(TSEQ / 128, BATCH), 256>>>(enc, out);
}

// round 8
// speedup vs baseline: 6.4714x; 1.9910x over previous
#include <cuda_runtime.h>
#include <cuda_fp16.h>
#include <cstdint>
#include <math.h>

// Bahdanau additive attention, sm_103 base target (no tcgen05).
// R8: score GEMM in SINGLE fp16 mma.sync (fp32 accum) — error budget
// ~1e-4 << 1e-3 threshold; 3x fewer MMAs than split-bf16. 3-stage
// cp.async pipeline. k1 restructured (Wa read once).

#define BATCH 32
#define TSEQ  2048
#define HDIM  1024
#define UDIM  1024
#define BT    (BATCH * TSEQ)

// ---------------------------------------------------------------- scratch
__device__ float g_score[BT];
__device__ float g_decproj[BATCH * UDIM];
__device__ __half g_enc_h[(size_t)BT * HDIM];     // 128 MB
__device__ __half g_ua_t[(size_t)UDIM * HDIM];    // transposed [U][H]

// ---------------------------------------------------------------- helpers
__device__ __forceinline__ uint32_t smem_u32(const void* p) {
    uint32_t a;
    asm("{ .reg .u64 t; cvta.to.shared.u64 t, %1; cvt.u32.u64 %0, t; }"
        : "=r"(a) : "l"(p));
    return a;
}
__device__ __forceinline__ uint32_t swz(uint32_t off) {
    return off ^ ((off >> 3) & 0x70);   // SW128 on 128B rows
}
__device__ __forceinline__ void cp16(uint32_t dst, const void* src) {
    asm volatile("cp.async.cg.shared.global [%0], [%1], 16;"
                 :: "r"(dst), "l"(src));
}
#define CP_COMMIT() asm volatile("cp.async.commit_group;" ::: "memory")
#define CP_WAIT2()  asm volatile("cp.async.wait_group 2;" ::: "memory")
#define CP_WAIT1()  asm volatile("cp.async.wait_group 1;" ::: "memory")
#define CP_WAIT0()  asm volatile("cp.async.wait_group 0;" ::: "memory")

__device__ __forceinline__ void ldm4(uint32_t& r0, uint32_t& r1,
                                     uint32_t& r2, uint32_t& r3, uint32_t a) {
    asm volatile("ldmatrix.sync.aligned.m8n8.x4.shared.b16 {%0,%1,%2,%3}, [%4];"
                 : "=r"(r0), "=r"(r1), "=r"(r2), "=r"(r3) : "r"(a));
}
__device__ __forceinline__ void mma16816(float* c, const uint32_t* a,
                                         const uint32_t* b) {
    asm volatile(
        "mma.sync.aligned.m16n8k16.row.col.f32.f16.f16.f32 "
        "{%0,%1,%2,%3}, {%4,%5,%6,%7}, {%8,%9}, {%0,%1,%2,%3};"
        : "+f"(c[0]), "+f"(c[1]), "+f"(c[2]), "+f"(c[3])
        : "r"(a[0]), "r"(a[1]), "r"(a[2]), "r"(a[3]), "r"(b[0]), "r"(b[1]));
}

// -------------------------------------------- P1: enc -> fp16 (vec4)
__global__ void p_split_enc(const float* __restrict__ enc) {
    size_t i = (size_t)blockIdx.x * blockDim.x + threadIdx.x;  // float4 idx
    float4 v = ((const float4*)enc)[i];
    ushort4 h;
    h.x = __half_as_ushort(__float2half(v.x));
    h.y = __half_as_ushort(__float2half(v.y));
    h.z = __half_as_ushort(__float2half(v.z));
    h.w = __half_as_ushort(__float2half(v.w));
    ((ushort4*)g_enc_h)[i] = h;
}

// ------------------------------- P2: Ua [H,U] -> transposed [U,H] fp16
__global__ void p_trans_ua(const float* __restrict__ Ua) {
    __shared__ float tile[32][33];
    int tx = threadIdx.x, ty = threadIdx.y;  // (32, 8)
    int u0 = blockIdx.x * 32, h0 = blockIdx.y * 32;
    #pragma unroll
    for (int j = 0; j < 4; j++)
        tile[ty + 8 * j][tx] = Ua[(size_t)(h0 + ty + 8 * j) * UDIM + u0 + tx];
    __syncthreads();
    #pragma unroll
    for (int j = 0; j < 4; j++) {
        float v = tile[tx][ty + 8 * j];
        g_ua_t[(size_t)(u0 + ty + 8 * j) * HDIM + h0 + tx] = __float2half(v);
    }
}

// --------------------------- K0: zero out (32K) and g_decproj (32K)
__global__ void k0_zero(float* out) {
    int i = blockIdx.x * blockDim.x + threadIdx.x;
    if (i < BATCH * HDIM) {
        out[i] = 0.0f;
        g_decproj[i] = 0.0f;
    }
}

// --------------------------------------------- K1: dec_proj = dec_hidden@Wa
// grid (8 u-blocks, 4 h-splits), 256 thr. Wa read exactly once chip-wide.
// Each thread: u = u0 + (tid&127), h-range 128, 32 batch accumulators.
__global__ void k1_decproj(const float* __restrict__ dec,
                           const float* __restrict__ Wa) {
    __shared__ float dec_s[BATCH][256];
    const int tid = threadIdx.x;
    const int u0 = blockIdx.x * 128;
    const int h0 = blockIdx.y * 256;
    // load dec[32][h0..h0+256]
    for (int i = tid; i < BATCH * 256; i += 256) {
        int b = i >> 8, h = i & 255;
        dec_s[b][h] = dec[b * HDIM + h0 + h];
    }
    __syncthreads();

    const int u = u0 + (tid & 127);
    const int hh = (tid >> 7) * 128;    // 0 or 128
    float acc[BATCH];
    #pragma unroll
    for (int b = 0; b < BATCH; b++) acc[b] = 0.0f;

    for (int h = 0; h < 128; h++) {
        float wa = Wa[(size_t)(h0 + hh + h) * UDIM + u];
        #pragma unroll
        for (int b = 0; b < BATCH; b++)
            acc[b] = fmaf(dec_s[b][hh + h], wa, acc[b]);
    }
    #pragma unroll
    for (int b = 0; b < BATCH; b++)
        atomicAdd(&g_decproj[b * UDIM + u], acc[b]);
}

// ------------------- K2: fused score via fp16 HMMA GEMM + epilogue
// grid 512 CTAs x 256 threads. CTA tile M=128 x N=128, K-chunk 64,
// 3-stage cp.async pipeline. Warp grid 4(m) x 2(n); warp tile m32 x n64.
#define K2_M   128
#define K2_N   128
#define K2_KC  64
#define NT_CNT (UDIM / K2_N)     // 8
#define KT_CNT (HDIM / K2_KC)    // 16
#define IT_TOT (NT_CNT * KT_CNT) // 128
#define N_STG  3

#define TILE_B   (128 * 128)     // [128 rows][64 fp16] = 16 KB
#define OFF_A    0
#define OFF_B    (TILE_B)
#define STAGE_B  (2 * TILE_B)    // 32 KB
#define SM_BIAS  (N_STG * STAGE_B)
#define SM_VA    (SM_BIAS + K2_N * 4)
#define SM_SCORE (SM_VA + K2_N * 4)
#define SM_TOTAL (SM_SCORE + K2_M * 4)   // ~99.8 KB

__device__ __forceinline__ void issue_chunk(uint32_t sb, int stage, int row0,
                                            int it, int tid) {
    const int nt = it >> 4, kt = it & 15;
    const int u0 = nt * K2_N;
    const int kg = kt * K2_KC;
    const uint32_t base = sb + stage * STAGE_B;
    #pragma unroll
    for (int i = 0; i < 4; i++) {
        int s = tid + i * 256;        // 0..1023
        int r = s >> 3, seg = s & 7;  // row, 16B segment
        uint32_t so = swz((uint32_t)(r * 128 + seg * 16));
        cp16(base + OFF_A + so, g_enc_h + (size_t)(row0 + r) * HDIM + kg + seg * 8);
        cp16(base + OFF_B + so, g_ua_t + (size_t)(u0 + r) * HDIM + kg + seg * 8);
    }
}

__global__ void __launch_bounds__(256, 1)
k2_score(const float* __restrict__ Va) {
    extern __shared__ char smem[];
    const uint32_t sb = smem_u32(smem);
    const int tid = threadIdx.x;
    const int lane = tid & 31;
    const int wid = tid >> 5;
    const int warp_m = wid >> 1;          // 0..3 -> m offset *32
    const int warp_n = wid & 1;           // 0..1 -> n offset *64
    const int row0 = blockIdx.x * K2_M;
    const int b = row0 / TSEQ;

    float* bias_s  = (float*)(smem + SM_BIAS);
    float* va_s    = (float*)(smem + SM_VA);
    float* score_s = (float*)(smem + SM_SCORE);
    if (tid < K2_M) score_s[tid] = 0.0f;

    // prologue: chunks 0,1 -> stages 0,1
    issue_chunk(sb, 0, row0, 0, tid);
    CP_COMMIT();
    issue_chunk(sb, 1, row0, 1, tid);
    CP_COMMIT();

    float c[2][8][4];

    for (int it = 0; it < IT_TOT; it++) {
        const int nt = it >> 4, kt = it & 15;
        const int stage = it % N_STG;

        if (it + 2 < IT_TOT) {
            issue_chunk(sb, (it + 2) % N_STG, row0, it + 2, tid);
            CP_COMMIT();
            CP_WAIT2();
        } else if (it + 1 < IT_TOT) {
            CP_WAIT1();
        } else {
            CP_WAIT0();
        }
        __syncthreads();

        if (kt == 0) {
            if (tid < K2_N) {
                bias_s[tid] = g_decproj[b * UDIM + nt * K2_N + tid];
                va_s[tid]   = Va[nt * K2_N + tid];
            }
            #pragma unroll
            for (int mi = 0; mi < 2; mi++)
                #pragma unroll
                for (int ni = 0; ni < 8; ni++)
                    #pragma unroll
                    for (int q = 0; q < 4; q++)
                        c[mi][ni][q] = 0.0f;
        }

        // ---- compute this chunk (4 x k16 steps)
        const uint32_t aT = sb + stage * STAGE_B + OFF_A;
        const uint32_t bT = sb + stage * STAGE_B + OFF_B;

        #pragma unroll
        for (int ks = 0; ks < 4; ks++) {
            const int kb = ks * 32;  // byte offset of k16 step
            uint32_t ar[2][4];
            #pragma unroll
            for (int mi = 0; mi < 2; mi++) {
                uint32_t rr = warp_m * 32 + mi * 16 + (lane & 15);
                uint32_t off = swz(rr * 128 + kb + (lane >> 4) * 16);
                ldm4(ar[mi][0], ar[mi][1], ar[mi][2], ar[mi][3], aT + off);
            }
            uint32_t br[8][2];
            #pragma unroll
            for (int np = 0; np < 4; np++) {   // each covers 2 n8 tiles
                uint32_t nr = warp_n * 64 + np * 16 + (lane & 7) +
                              ((lane >> 4) ? 8u : 0u);
                uint32_t off = swz(nr * 128 + kb + ((lane >> 3) & 1) * 16);
                uint32_t r0, r1, r2, r3;
                ldm4(r0, r1, r2, r3, bT + off);
                br[np * 2][0] = r0;     br[np * 2][1] = r1;
                br[np * 2 + 1][0] = r2; br[np * 2 + 1][1] = r3;
            }
            #pragma unroll
            for (int mi = 0; mi < 2; mi++)
                #pragma unroll
                for (int ni = 0; ni < 8; ni++)
                    mma16816(c[mi][ni], ar[mi], br[ni]);
        }

        // ---- epilogue at end of each N-slab
        if (kt == KT_CNT - 1) {
            const int qc = lane & 3;
            const int gl = lane >> 2;
            #pragma unroll
            for (int mi = 0; mi < 2; mi++) {
                float s0 = 0.0f, s1 = 0.0f;  // rows r and r+8
                #pragma unroll
                for (int ni = 0; ni < 8; ni++) {
                    int col = warp_n * 64 + ni * 8 + qc * 2;
                    float b0 = bias_s[col], b1 = bias_s[col + 1];
                    float v0 = va_s[col],  v1 = va_s[col + 1];
                    s0 = fmaf(v0, tanhf(c[mi][ni][0] + b0), s0);
                    s0 = fmaf(v1, tanhf(c[mi][ni][1] + b1), s0);
                    s1 = fmaf(v0, tanhf(c[mi][ni][2] + b0), s1);
                    s1 = fmaf(v1, tanhf(c[mi][ni][3] + b1), s1);
                }
                s0 += __shfl_xor_sync(0xFFFFFFFF, s0, 1);
                s0 += __shfl_xor_sync(0xFFFFFFFF, s0, 2);
                s1 += __shfl_xor_sync(0xFFFFFFFF, s1, 1);
                s1 += __shfl_xor_sync(0xFFFFFFFF, s1, 2);
                if (qc == 0) {
                    int r = warp_m * 32 + mi * 16 + gl;
                    atomicAdd(&score_s[r], s0);
                    atomicAdd(&score_s[r + 8], s1);
                }
            }
        }
        __syncthreads();   // stage consumed before reuse; bias stable
    }

    if (tid < K2_M) g_score[row0 + tid] = score_s[tid];
}

// ---------------------------------------------- K3: softmax over T (in place)
__global__ void k3_softmax() {
    __shared__ float red[256];
    const int b = blockIdx.x;
    const int tid = threadIdx.x;
    float* row = g_score + (size_t)b * TSEQ;

    float m = -1e30f;
    for (int t = tid; t < TSEQ; t += 256) m = fmaxf(m, row[t]);
    red[tid] = m; __syncthreads();
    for (int s = 128; s > 0; s >>= 1) {
        if (tid < s) red[tid] = fmaxf(red[tid], red[tid + s]);
        __syncthreads();
    }
    m = red[0];
    __syncthreads();

    float sum = 0.0f;
    for (int t = tid; t < TSEQ; t += 256) {
        float e = __expf(row[t] - m);
        row[t] = e;
        sum += e;
    }
    red[tid] = sum; __syncthreads();
    for (int s = 128; s > 0; s >>= 1) {
        if (tid < s) red[tid] += red[tid + s];
        __syncthreads();
    }
    float inv = 1.0f / red[0];
    __syncthreads();
    for (int t = tid; t < TSEQ; t += 256) row[t] *= inv;
}

// ------------------------- K4: context[b,h] = sum_t alpha[b,t]*enc[b,t,h]
__global__ void k4_context(const float* __restrict__ enc, float* __restrict__ out) {
    __shared__ float al[128];
    const int b = blockIdx.y;
    const int t0 = blockIdx.x * 128;
    const int tid = threadIdx.x;
    if (tid < 128) al[tid] = g_score[(size_t)b * TSEQ + t0 + tid];
    __syncthreads();

    float4 acc = make_float4(0.f, 0.f, 0.f, 0.f);
    const float* base = enc + ((size_t)b * TSEQ + t0) * HDIM + tid * 4;
    #pragma unroll 4
    for (int tt = 0; tt < 128; tt++) {
        float a = al[tt];
        float4 e = *(const float4*)(base + (size_t)tt * HDIM);
        acc.x = fmaf(a, e.x, acc.x);
        acc.y = fmaf(a, e.y, acc.y);
        acc.z = fmaf(a, e.z, acc.z);
        acc.w = fmaf(a, e.w, acc.w);
    }
    float* o = out + (size_t)b * HDIM + tid * 4;
    atomicAdd(o + 0, acc.x);
    atomicAdd(o + 1, acc.y);
    atomicAdd(o + 2, acc.z);
    atomicAdd(o + 3, acc.w);
}

// ------------------------------------------------------------------- launcher
extern "C" void kernel_launch(void* const* d_in, const int* in_sizes, int n_in,
                              void* d_out, int out_size) {
    const float* enc = (const float*)d_in[0];
    const float* dec = (const float*)d_in[1];
    const float* Wa  = (const float*)d_in[2];
    const float* Ua  = (const float*)d_in[3];
    const float* Va  = (const float*)d_in[4];
    float* out = (float*)d_out;
    (void)in_sizes; (void)n_in; (void)out_size;

    cudaFuncSetAttribute(k2_score, cudaFuncAttributeMaxDynamicSharedMemorySize,
                         SM_TOTAL);

    k0_zero<<<(BATCH * HDIM + 255) / 256, 256>>>(out);
    p_split_enc<<<(BT * HDIM / 4) / 256, 256>>>(enc);
    p_trans_ua<<<dim3(UDIM / 32, HDIM / 32), dim3(32, 8)>>>(Ua);
    k1_decproj<<<dim3(8, 4), 256>>>(dec, Wa);
    k2_score<<<BT / K2_M, 256, SM_TOTAL>>>(Va);
    k3_softmax<<<BATCH, 256>>>();
    k4_context<<<dim3(TSEQ / 128, BATCH), 256>>>(enc, out);
}

// round 9
// speedup vs baseline: 8.0522x; 1.2443x over previous
#include <cuda_runtime.h>
#include <cuda_fp16.h>
#include <cstdint>
#include <math.h>

// Bahdanau additive attention, sm_103 base target (no tcgen05).
// R9: k2 at occupancy 2 (forced <=128 regs, 2 CTAs/SM overlap stalls);
// k1 parallelized 32->128 blocks; k4 reads fp16 enc (half traffic).

#define BATCH 32
#define TSEQ  2048
#define HDIM  1024
#define UDIM  1024
#define BT    (BATCH * TSEQ)

// ---------------------------------------------------------------- scratch
__device__ float g_score[BT];
__device__ float g_decproj[BATCH * UDIM];
__device__ __half g_enc_h[(size_t)BT * HDIM];     // 128 MB
__device__ __half g_ua_t[(size_t)UDIM * HDIM];    // transposed [U][H]

// ---------------------------------------------------------------- helpers
__device__ __forceinline__ uint32_t smem_u32(const void* p) {
    uint32_t a;
    asm("{ .reg .u64 t; cvta.to.shared.u64 t, %1; cvt.u32.u64 %0, t; }"
        : "=r"(a) : "l"(p));
    return a;
}
__device__ __forceinline__ uint32_t swz(uint32_t off) {
    return off ^ ((off >> 3) & 0x70);   // SW128 on 128B rows
}
__device__ __forceinline__ void cp16(uint32_t dst, const void* src) {
    asm volatile("cp.async.cg.shared.global [%0], [%1], 16;"
                 :: "r"(dst), "l"(src));
}
#define CP_COMMIT() asm volatile("cp.async.commit_group;" ::: "memory")
#define CP_WAIT2()  asm volatile("cp.async.wait_group 2;" ::: "memory")
#define CP_WAIT1()  asm volatile("cp.async.wait_group 1;" ::: "memory")
#define CP_WAIT0()  asm volatile("cp.async.wait_group 0;" ::: "memory")

__device__ __forceinline__ void ldm4(uint32_t& r0, uint32_t& r1,
                                     uint32_t& r2, uint32_t& r3, uint32_t a) {
    asm volatile("ldmatrix.sync.aligned.m8n8.x4.shared.b16 {%0,%1,%2,%3}, [%4];"
                 : "=r"(r0), "=r"(r1), "=r"(r2), "=r"(r3) : "r"(a));
}
__device__ __forceinline__ void mma16816(float* c, const uint32_t* a,
                                         const uint32_t* b) {
    asm volatile(
        "mma.sync.aligned.m16n8k16.row.col.f32.f16.f16.f32 "
        "{%0,%1,%2,%3}, {%4,%5,%6,%7}, {%8,%9}, {%0,%1,%2,%3};"
        : "+f"(c[0]), "+f"(c[1]), "+f"(c[2]), "+f"(c[3])
        : "r"(a[0]), "r"(a[1]), "r"(a[2]), "r"(a[3]), "r"(b[0]), "r"(b[1]));
}

// -------------------------------------------- P1: enc -> fp16 (vec4)
__global__ void p_split_enc(const float* __restrict__ enc) {
    size_t i = (size_t)blockIdx.x * blockDim.x + threadIdx.x;  // float4 idx
    float4 v = ((const float4*)enc)[i];
    ushort4 h;
    h.x = __half_as_ushort(__float2half(v.x));
    h.y = __half_as_ushort(__float2half(v.y));
    h.z = __half_as_ushort(__float2half(v.z));
    h.w = __half_as_ushort(__float2half(v.w));
    ((ushort4*)g_enc_h)[i] = h;
}

// ------------------------------- P2: Ua [H,U] -> transposed [U,H] fp16
__global__ void p_trans_ua(const float* __restrict__ Ua) {
    __shared__ float tile[32][33];
    int tx = threadIdx.x, ty = threadIdx.y;  // (32, 8)
    int u0 = blockIdx.x * 32, h0 = blockIdx.y * 32;
    #pragma unroll
    for (int j = 0; j < 4; j++)
        tile[ty + 8 * j][tx] = Ua[(size_t)(h0 + ty + 8 * j) * UDIM + u0 + tx];
    __syncthreads();
    #pragma unroll
    for (int j = 0; j < 4; j++) {
        float v = tile[tx][ty + 8 * j];
        g_ua_t[(size_t)(u0 + ty + 8 * j) * HDIM + h0 + tx] = __float2half(v);
    }
}

// --------------------------- K0: zero out (32K) and g_decproj (32K)
__global__ void k0_zero(float* out) {
    int i = blockIdx.x * blockDim.x + threadIdx.x;
    if (i < BATCH * HDIM) {
        out[i] = 0.0f;
        g_decproj[i] = 0.0f;
    }
}

// --------------------------------------------- K1: dec_proj = dec_hidden@Wa
// grid (8 u-blocks, 16 h-splits) = 128 blocks, 256 thr. Wa read once.
// Thread: u = u0 + (tid&127), 32-h slice, 32 batch accumulators.
__global__ void k1_decproj(const float* __restrict__ dec,
                           const float* __restrict__ Wa) {
    __shared__ float dec_s[BATCH][64];
    const int tid = threadIdx.x;
    const int u0 = blockIdx.x * 128;
    const int h0 = blockIdx.y * 64;
    for (int i = tid; i < BATCH * 64; i += 256) {
        int b = i >> 6, h = i & 63;
        dec_s[b][h] = dec[b * HDIM + h0 + h];
    }
    __syncthreads();

    const int u = u0 + (tid & 127);
    const int hh = (tid >> 7) * 32;     // 0 or 32
    float acc[BATCH];
    #pragma unroll
    for (int b = 0; b < BATCH; b++) acc[b] = 0.0f;

    #pragma unroll 4
    for (int h = 0; h < 32; h++) {
        float wa = Wa[(size_t)(h0 + hh + h) * UDIM + u];
        #pragma unroll
        for (int b = 0; b < BATCH; b++)
            acc[b] = fmaf(dec_s[b][hh + h], wa, acc[b]);
    }
    #pragma unroll
    for (int b = 0; b < BATCH; b++)
        atomicAdd(&g_decproj[b * UDIM + u], acc[b]);
}

// ------------------- K2: fused score via fp16 HMMA GEMM + epilogue
// grid 512 CTAs x 256 threads, OCCUPANCY 2 (2 CTAs/SM overlap stalls).
// CTA tile M=128 x N=128, K-chunk 64, 3-stage cp.async pipeline.
#define K2_M   128
#define K2_N   128
#define K2_KC  64
#define NT_CNT (UDIM / K2_N)     // 8
#define KT_CNT (HDIM / K2_KC)    // 16
#define IT_TOT (NT_CNT * KT_CNT) // 128
#define N_STG  3

#define TILE_B   (128 * 128)     // [128 rows][64 fp16] = 16 KB
#define OFF_A    0
#define OFF_B    (TILE_B)
#define STAGE_B  (2 * TILE_B)    // 32 KB
#define SM_BIAS  (N_STG * STAGE_B)
#define SM_VA    (SM_BIAS + K2_N * 4)
#define SM_SCORE (SM_VA + K2_N * 4)
#define SM_TOTAL (SM_SCORE + K2_M * 4)   // ~99.8 KB ; 2 CTAs = 199.7 <= 228

__device__ __forceinline__ void issue_chunk(uint32_t sb, int stage, int row0,
                                            int it, int tid) {
    const int nt = it >> 4, kt = it & 15;
    const int u0 = nt * K2_N;
    const int kg = kt * K2_KC;
    const uint32_t base = sb + stage * STAGE_B;
    #pragma unroll
    for (int i = 0; i < 4; i++) {
        int s = tid + i * 256;        // 0..1023
        int r = s >> 3, seg = s & 7;  // row, 16B segment
        uint32_t so = swz((uint32_t)(r * 128 + seg * 16));
        cp16(base + OFF_A + so, g_enc_h + (size_t)(row0 + r) * HDIM + kg + seg * 8);
        cp16(base + OFF_B + so, g_ua_t + (size_t)(u0 + r) * HDIM + kg + seg * 8);
    }
}

__global__ void __launch_bounds__(256, 2)
k2_score(const float* __restrict__ Va) {
    extern __shared__ char smem[];
    const uint32_t sb = smem_u32(smem);
    const int tid = threadIdx.x;
    const int lane = tid & 31;
    const int wid = tid >> 5;
    const int warp_m = wid >> 1;          // 0..3 -> m offset *32
    const int warp_n = wid & 1;           // 0..1 -> n offset *64
    const int row0 = blockIdx.x * K2_M;
    const int b = row0 / TSEQ;

    float* bias_s  = (float*)(smem + SM_BIAS);
    float* va_s    = (float*)(smem + SM_VA);
    float* score_s = (float*)(smem + SM_SCORE);
    if (tid < K2_M) score_s[tid] = 0.0f;

    // prologue: chunks 0,1 -> stages 0,1
    issue_chunk(sb, 0, row0, 0, tid);
    CP_COMMIT();
    issue_chunk(sb, 1, row0, 1, tid);
    CP_COMMIT();

    float c[2][8][4];

    for (int it = 0; it < IT_TOT; it++) {
        const int nt = it >> 4, kt = it & 15;
        const int stage = it % N_STG;

        if (it + 2 < IT_TOT) {
            issue_chunk(sb, (it + 2) % N_STG, row0, it + 2, tid);
            CP_COMMIT();
            CP_WAIT2();
        } else if (it + 1 < IT_TOT) {
            CP_WAIT1();
        } else {
            CP_WAIT0();
        }
        __syncthreads();

        if (kt == 0) {
            if (tid < K2_N) {
                bias_s[tid] = g_decproj[b * UDIM + nt * K2_N + tid];
                va_s[tid]   = Va[nt * K2_N + tid];
            }
            #pragma unroll
            for (int mi = 0; mi < 2; mi++)
                #pragma unroll
                for (int ni = 0; ni < 8; ni++)
                    #pragma unroll
                    for (int q = 0; q < 4; q++)
                        c[mi][ni][q] = 0.0f;
        }

        // ---- compute this chunk (4 x k16 steps)
        const uint32_t aT = sb + stage * STAGE_B + OFF_A;
        const uint32_t bT = sb + stage * STAGE_B + OFF_B;

        #pragma unroll
        for (int ks = 0; ks < 4; ks++) {
            const int kb = ks * 32;  // byte offset of k16 step
            uint32_t ar[2][4];
            #pragma unroll
            for (int mi = 0; mi < 2; mi++) {
                uint32_t rr = warp_m * 32 + mi * 16 + (lane & 15);
                uint32_t off = swz(rr * 128 + kb + (lane >> 4) * 16);
                ldm4(ar[mi][0], ar[mi][1], ar[mi][2], ar[mi][3], aT + off);
            }
            uint32_t br[8][2];
            #pragma unroll
            for (int np = 0; np < 4; np++) {   // each covers 2 n8 tiles
                uint32_t nr = warp_n * 64 + np * 16 + (lane & 7) +
                              ((lane >> 4) ? 8u : 0u);
                uint32_t off = swz(nr * 128 + kb + ((lane >> 3) & 1) * 16);
                uint32_t r0, r1, r2, r3;
                ldm4(r0, r1, r2, r3, bT + off);
                br[np * 2][0] = r0;     br[np * 2][1] = r1;
                br[np * 2 + 1][0] = r2; br[np * 2 + 1][1] = r3;
            }
            #pragma unroll
            for (int mi = 0; mi < 2; mi++)
                #pragma unroll
                for (int ni = 0; ni < 8; ni++)
                    mma16816(c[mi][ni], ar[mi], br[ni]);
        }

        // ---- epilogue at end of each N-slab
        if (kt == KT_CNT - 1) {
            const int qc = lane & 3;
            const int gl = lane >> 2;
            #pragma unroll
            for (int mi = 0; mi < 2; mi++) {
                float s0 = 0.0f, s1 = 0.0f;  // rows r and r+8
                #pragma unroll
                for (int ni = 0; ni < 8; ni++) {
                    int col = warp_n * 64 + ni * 8 + qc * 2;
                    float b0 = bias_s[col], b1 = bias_s[col + 1];
                    float v0 = va_s[col],  v1 = va_s[col + 1];
                    s0 = fmaf(v0, tanhf(c[mi][ni][0] + b0), s0);
                    s0 = fmaf(v1, tanhf(c[mi][ni][1] + b1), s0);
                    s1 = fmaf(v0, tanhf(c[mi][ni][2] + b0), s1);
                    s1 = fmaf(v1, tanhf(c[mi][ni][3] + b1), s1);
                }
                s0 += __shfl_xor_sync(0xFFFFFFFF, s0, 1);
                s0 += __shfl_xor_sync(0xFFFFFFFF, s0, 2);
                s1 += __shfl_xor_sync(0xFFFFFFFF, s1, 1);
                s1 += __shfl_xor_sync(0xFFFFFFFF, s1, 2);
                if (qc == 0) {
                    int r = warp_m * 32 + mi * 16 + gl;
                    atomicAdd(&score_s[r], s0);
                    atomicAdd(&score_s[r + 8], s1);
                }
            }
        }
        __syncthreads();   // stage consumed before reuse; bias stable
    }

    if (tid < K2_M) g_score[row0 + tid] = score_s[tid];
}

// ---------------------------------------------- K3: softmax over T (in place)
__global__ void k3_softmax() {
    __shared__ float red[256];
    const int b = blockIdx.x;
    const int tid = threadIdx.x;
    float* row = g_score + (size_t)b * TSEQ;

    float m = -1e30f;
    for (int t = tid; t < TSEQ; t += 256) m = fmaxf(m, row[t]);
    red[tid] = m; __syncthreads();
    for (int s = 128; s > 0; s >>= 1) {
        if (tid < s) red[tid] = fmaxf(red[tid], red[tid + s]);
        __syncthreads();
    }
    m = red[0];
    __syncthreads();

    float sum = 0.0f;
    for (int t = tid; t < TSEQ; t += 256) {
        float e = __expf(row[t] - m);
        row[t] = e;
        sum += e;
    }
    red[tid] = sum; __syncthreads();
    for (int s = 128; s > 0; s >>= 1) {
        if (tid < s) red[tid] += red[tid + s];
        __syncthreads();
    }
    float inv = 1.0f / red[0];
    __syncthreads();
    for (int t = tid; t < TSEQ; t += 256) row[t] *= inv;
}

// ------------------------- K4: context[b,h] = sum_t alpha[b,t]*enc_h[b,t,h]
// Reads fp16 enc (halves DRAM traffic; adds ~2.4e-4 independent rounding).
__global__ void k4_context(float* __restrict__ out) {
    __shared__ float al[128];
    const int b = blockIdx.y;
    const int t0 = blockIdx.x * 128;
    const int tid = threadIdx.x;
    if (tid < 128) al[tid] = g_score[(size_t)b * TSEQ + t0 + tid];
    __syncthreads();

    float4 acc = make_float4(0.f, 0.f, 0.f, 0.f);
    const __half* base = g_enc_h + ((size_t)b * TSEQ + t0) * HDIM + tid * 4;
    #pragma unroll 4
    for (int tt = 0; tt < 128; tt++) {
        float a = al[tt];
        uint2 e = *(const uint2*)(base + (size_t)tt * HDIM);
        float2 f01 = __half22float2(*reinterpret_cast<const __half2*>(&e.x));
        float2 f23 = __half22float2(*reinterpret_cast<const __half2*>(&e.y));
        acc.x = fmaf(a, f01.x, acc.x);
        acc.y = fmaf(a, f01.y, acc.y);
        acc.z = fmaf(a, f23.x, acc.z);
        acc.w = fmaf(a, f23.y, acc.w);
    }
    float* o = out + (size_t)b * HDIM + tid * 4;
    atomicAdd(o + 0, acc.x);
    atomicAdd(o + 1, acc.y);
    atomicAdd(o + 2, acc.z);
    atomicAdd(o + 3, acc.w);
}

// ------------------------------------------------------------------- launcher
extern "C" void kernel_launch(void* const* d_in, const int* in_sizes, int n_in,
                              void* d_out, int out_size) {
    const float* enc = (const float*)d_in[0];
    const float* dec = (const float*)d_in[1];
    const float* Wa  = (const float*)d_in[2];
    const float* Ua  = (const float*)d_in[3];
    const float* Va  = (const float*)d_in[4];
    float* out = (float*)d_out;
    (void)in_sizes; (void)n_in; (void)out_size;

    cudaFuncSetAttribute(k2_score, cudaFuncAttributeMaxDynamicSharedMemorySize,
                         SM_TOTAL);

    k0_zero<<<(BATCH * HDIM + 255) / 256, 256>>>(out);
    p_split_enc<<<(BT * HDIM / 4) / 256, 256>>>(enc);
    p_trans_ua<<<dim3(UDIM / 32, HDIM / 32), dim3(32, 8)>>>(Ua);
    k1_decproj<<<dim3(8, 16), 256>>>(dec, Wa);
    k2_score<<<BT / K2_M, 256, SM_TOTAL>>>(Va);
    k3_softmax<<<BATCH, 256>>>();
    k4_context<<<dim3(TSEQ / 128, BATCH), 256>>>(out);
}

// round 10
// speedup vs baseline: 8.4135x; 1.0449x over previous
#include <cuda_runtime.h>
#include <cuda_fp16.h>
#include <cstdint>
#include <math.h>

// Bahdanau additive attention, sm_103 base target (no tcgen05).
// R10: k2 split over U (score[t] = sum_u Va[u]*tanh(pre[t,u]) is a sum of
// independent u-terms) -> grid (512,2), half the per-CTA work, same total
// L2 traffic, ~1% wave tail instead of 15%. Partial scores atomicAdd.
// k4 chunk 256. k3 1024 threads.

#define BATCH 32
#define TSEQ  2048
#define HDIM  1024
#define UDIM  1024
#define BT    (BATCH * TSEQ)

// ---------------------------------------------------------------- scratch
__device__ float g_score[BT];
__device__ float g_decproj[BATCH * UDIM];
__device__ __half g_enc_h[(size_t)BT * HDIM];     // 128 MB
__device__ __half g_ua_t[(size_t)UDIM * HDIM];    // transposed [U][H]

// ---------------------------------------------------------------- helpers
__device__ __forceinline__ uint32_t smem_u32(const void* p) {
    uint32_t a;
    asm("{ .reg .u64 t; cvta.to.shared.u64 t, %1; cvt.u32.u64 %0, t; }"
        : "=r"(a) : "l"(p));
    return a;
}
__device__ __forceinline__ uint32_t swz(uint32_t off) {
    return off ^ ((off >> 3) & 0x70);   // SW128 on 128B rows
}
__device__ __forceinline__ void cp16(uint32_t dst, const void* src) {
    asm volatile("cp.async.cg.shared.global [%0], [%1], 16;"
                 :: "r"(dst), "l"(src));
}
#define CP_COMMIT() asm volatile("cp.async.commit_group;" ::: "memory")
#define CP_WAIT2()  asm volatile("cp.async.wait_group 2;" ::: "memory")
#define CP_WAIT1()  asm volatile("cp.async.wait_group 1;" ::: "memory")
#define CP_WAIT0()  asm volatile("cp.async.wait_group 0;" ::: "memory")

__device__ __forceinline__ void ldm4(uint32_t& r0, uint32_t& r1,
                                     uint32_t& r2, uint32_t& r3, uint32_t a) {
    asm volatile("ldmatrix.sync.aligned.m8n8.x4.shared.b16 {%0,%1,%2,%3}, [%4];"
                 : "=r"(r0), "=r"(r1), "=r"(r2), "=r"(r3) : "r"(a));
}
__device__ __forceinline__ void mma16816(float* c, const uint32_t* a,
                                         const uint32_t* b) {
    asm volatile(
        "mma.sync.aligned.m16n8k16.row.col.f32.f16.f16.f32 "
        "{%0,%1,%2,%3}, {%4,%5,%6,%7}, {%8,%9}, {%0,%1,%2,%3};"
        : "+f"(c[0]), "+f"(c[1]), "+f"(c[2]), "+f"(c[3])
        : "r"(a[0]), "r"(a[1]), "r"(a[2]), "r"(a[3]), "r"(b[0]), "r"(b[1]));
}

// -------------------------------------------- P1: enc -> fp16 (vec4)
__global__ void p_split_enc(const float* __restrict__ enc) {
    size_t i = (size_t)blockIdx.x * blockDim.x + threadIdx.x;  // float4 idx
    float4 v = ((const float4*)enc)[i];
    ushort4 h;
    h.x = __half_as_ushort(__float2half(v.x));
    h.y = __half_as_ushort(__float2half(v.y));
    h.z = __half_as_ushort(__float2half(v.z));
    h.w = __half_as_ushort(__float2half(v.w));
    ((ushort4*)g_enc_h)[i] = h;
}

// ------------------------------- P2: Ua [H,U] -> transposed [U,H] fp16
__global__ void p_trans_ua(const float* __restrict__ Ua) {
    __shared__ float tile[32][33];
    int tx = threadIdx.x, ty = threadIdx.y;  // (32, 8)
    int u0 = blockIdx.x * 32, h0 = blockIdx.y * 32;
    #pragma unroll
    for (int j = 0; j < 4; j++)
        tile[ty + 8 * j][tx] = Ua[(size_t)(h0 + ty + 8 * j) * UDIM + u0 + tx];
    __syncthreads();
    #pragma unroll
    for (int j = 0; j < 4; j++) {
        float v = tile[tx][ty + 8 * j];
        g_ua_t[(size_t)(u0 + ty + 8 * j) * HDIM + h0 + tx] = __float2half(v);
    }
}

// ------------- K0: zero g_score (64K), out (32K), g_decproj (32K)
__global__ void k0_zero(float* out) {
    int i = blockIdx.x * blockDim.x + threadIdx.x;   // 0..65535
    g_score[i] = 0.0f;
    if (i < BATCH * HDIM) {
        out[i] = 0.0f;
        g_decproj[i] = 0.0f;
    }
}

// --------------------------------------------- K1: dec_proj = dec_hidden@Wa
// grid (8 u-blocks, 16 h-splits) = 128 blocks, 256 thr. Wa read once.
__global__ void k1_decproj(const float* __restrict__ dec,
                           const float* __restrict__ Wa) {
    __shared__ float dec_s[BATCH][64];
    const int tid = threadIdx.x;
    const int u0 = blockIdx.x * 128;
    const int h0 = blockIdx.y * 64;
    for (int i = tid; i < BATCH * 64; i += 256) {
        int b = i >> 6, h = i & 63;
        dec_s[b][h] = dec[b * HDIM + h0 + h];
    }
    __syncthreads();

    const int u = u0 + (tid & 127);
    const int hh = (tid >> 7) * 32;     // 0 or 32
    float acc[BATCH];
    #pragma unroll
    for (int b = 0; b < BATCH; b++) acc[b] = 0.0f;

    #pragma unroll 4
    for (int h = 0; h < 32; h++) {
        float wa = Wa[(size_t)(h0 + hh + h) * UDIM + u];
        #pragma unroll
        for (int b = 0; b < BATCH; b++)
            acc[b] = fmaf(dec_s[b][hh + h], wa, acc[b]);
    }
    #pragma unroll
    for (int b = 0; b < BATCH; b++)
        atomicAdd(&g_decproj[b * UDIM + u], acc[b]);
}

// ------------------- K2: fused score via fp16 HMMA GEMM + epilogue
// grid (512 m-blocks, 2 u-halves) x 256 threads, occupancy 2.
// CTA: M=128 rows x U-half (4 N-slabs of 128), K-chunk 64, 3-stage
// cp.async pipeline. Warp grid 4(m) x 2(n). Partial score -> atomicAdd.
#define K2_M   128
#define K2_N   128
#define K2_KC  64
#define NT_CNT 4                 // N-slabs per CTA (half of U)
#define KT_CNT (HDIM / K2_KC)    // 16
#define IT_TOT (NT_CNT * KT_CNT) // 64
#define N_STG  3

#define TILE_B   (128 * 128)     // [128 rows][64 fp16] = 16 KB
#define OFF_A    0
#define OFF_B    (TILE_B)
#define STAGE_B  (2 * TILE_B)    // 32 KB
#define SM_BIAS  (N_STG * STAGE_B)
#define SM_VA    (SM_BIAS + K2_N * 4)
#define SM_SCORE (SM_VA + K2_N * 4)
#define SM_TOTAL (SM_SCORE + K2_M * 4)   // ~99.8 KB ; 2 CTAs = 199.7 <= 228

__device__ __forceinline__ void issue_chunk(uint32_t sb, int stage, int row0,
                                            int ubase, int it, int tid) {
    const int nt = it >> 4, kt = it & 15;
    const int u0 = ubase + nt * K2_N;
    const int kg = kt * K2_KC;
    const uint32_t base = sb + stage * STAGE_B;
    #pragma unroll
    for (int i = 0; i < 4; i++) {
        int s = tid + i * 256;        // 0..1023
        int r = s >> 3, seg = s & 7;  // row, 16B segment
        uint32_t so = swz((uint32_t)(r * 128 + seg * 16));
        cp16(base + OFF_A + so, g_enc_h + (size_t)(row0 + r) * HDIM + kg + seg * 8);
        cp16(base + OFF_B + so, g_ua_t + (size_t)(u0 + r) * HDIM + kg + seg * 8);
    }
}

__global__ void __launch_bounds__(256, 2)
k2_score(const float* __restrict__ Va) {
    extern __shared__ char smem[];
    const uint32_t sb = smem_u32(smem);
    const int tid = threadIdx.x;
    const int lane = tid & 31;
    const int wid = tid >> 5;
    const int warp_m = wid >> 1;          // 0..3 -> m offset *32
    const int warp_n = wid & 1;           // 0..1 -> n offset *64
    const int row0 = blockIdx.x * K2_M;
    const int ubase = blockIdx.y * (NT_CNT * K2_N);   // 0 or 512
    const int b = row0 / TSEQ;

    float* bias_s  = (float*)(smem + SM_BIAS);
    float* va_s    = (float*)(smem + SM_VA);
    float* score_s = (float*)(smem + SM_SCORE);
    if (tid < K2_M) score_s[tid] = 0.0f;

    // prologue: chunks 0,1 -> stages 0,1
    issue_chunk(sb, 0, row0, ubase, 0, tid);
    CP_COMMIT();
    issue_chunk(sb, 1, row0, ubase, 1, tid);
    CP_COMMIT();

    float c[2][8][4];

    for (int it = 0; it < IT_TOT; it++) {
        const int nt = it >> 4, kt = it & 15;
        const int stage = it % N_STG;

        if (it + 2 < IT_TOT) {
            issue_chunk(sb, (it + 2) % N_STG, row0, ubase, it + 2, tid);
            CP_COMMIT();
            CP_WAIT2();
        } else if (it + 1 < IT_TOT) {
            CP_WAIT1();
        } else {
            CP_WAIT0();
        }
        __syncthreads();

        if (kt == 0) {
            if (tid < K2_N) {
                bias_s[tid] = g_decproj[b * UDIM + ubase + nt * K2_N + tid];
                va_s[tid]   = Va[ubase + nt * K2_N + tid];
            }
            #pragma unroll
            for (int mi = 0; mi < 2; mi++)
                #pragma unroll
                for (int ni = 0; ni < 8; ni++)
                    #pragma unroll
                    for (int q = 0; q < 4; q++)
                        c[mi][ni][q] = 0.0f;
        }

        // ---- compute this chunk (4 x k16 steps)
        const uint32_t aT = sb + stage * STAGE_B + OFF_A;
        const uint32_t bT = sb + stage * STAGE_B + OFF_B;

        #pragma unroll
        for (int ks = 0; ks < 4; ks++) {
            const int kb = ks * 32;  // byte offset of k16 step
            uint32_t ar[2][4];
            #pragma unroll
            for (int mi = 0; mi < 2; mi++) {
                uint32_t rr = warp_m * 32 + mi * 16 + (lane & 15);
                uint32_t off = swz(rr * 128 + kb + (lane >> 4) * 16);
                ldm4(ar[mi][0], ar[mi][1], ar[mi][2], ar[mi][3], aT + off);
            }
            uint32_t br[8][2];
            #pragma unroll
            for (int np = 0; np < 4; np++) {   // each covers 2 n8 tiles
                uint32_t nr = warp_n * 64 + np * 16 + (lane & 7) +
                              ((lane >> 4) ? 8u : 0u);
                uint32_t off = swz(nr * 128 + kb + ((lane >> 3) & 1) * 16);
                uint32_t r0, r1, r2, r3;
                ldm4(r0, r1, r2, r3, bT + off);
                br[np * 2][0] = r0;     br[np * 2][1] = r1;
                br[np * 2 + 1][0] = r2; br[np * 2 + 1][1] = r3;
            }
            #pragma unroll
            for (int mi = 0; mi < 2; mi++)
                #pragma unroll
                for (int ni = 0; ni < 8; ni++)
                    mma16816(c[mi][ni], ar[mi], br[ni]);
        }

        // ---- epilogue at end of each N-slab
        if (kt == KT_CNT - 1) {
            const int qc = lane & 3;
            const int gl = lane >> 2;
            #pragma unroll
            for (int mi = 0; mi < 2; mi++) {
                float s0 = 0.0f, s1 = 0.0f;  // rows r and r+8
                #pragma unroll
                for (int ni = 0; ni < 8; ni++) {
                    int col = warp_n * 64 + ni * 8 + qc * 2;
                    float b0 = bias_s[col], b1 = bias_s[col + 1];
                    float v0 = va_s[col],  v1 = va_s[col + 1];
                    s0 = fmaf(v0, tanhf(c[mi][ni][0] + b0), s0);
                    s0 = fmaf(v1, tanhf(c[mi][ni][1] + b1), s0);
                    s1 = fmaf(v0, tanhf(c[mi][ni][2] + b0), s1);
                    s1 = fmaf(v1, tanhf(c[mi][ni][3] + b1), s1);
                }
                s0 += __shfl_xor_sync(0xFFFFFFFF, s0, 1);
                s0 += __shfl_xor_sync(0xFFFFFFFF, s0, 2);
                s1 += __shfl_xor_sync(0xFFFFFFFF, s1, 1);
                s1 += __shfl_xor_sync(0xFFFFFFFF, s1, 2);
                if (qc == 0) {
                    int r = warp_m * 32 + mi * 16 + gl;
                    atomicAdd(&score_s[r], s0);
                    atomicAdd(&score_s[r + 8], s1);
                }
            }
        }
        __syncthreads();   // stage consumed before reuse; bias stable
    }

    if (tid < K2_M) atomicAdd(&g_score[row0 + tid], score_s[tid]);
}

// ---------------------------------------------- K3: softmax over T (in place)
__global__ void k3_softmax() {
    __shared__ float red[1024];
    const int b = blockIdx.x;
    const int tid = threadIdx.x;
    float* row = g_score + (size_t)b * TSEQ;

    float m = fmaxf(row[tid], row[tid + 1024]);
    red[tid] = m; __syncthreads();
    for (int s = 512; s > 0; s >>= 1) {
        if (tid < s) red[tid] = fmaxf(red[tid], red[tid + s]);
        __syncthreads();
    }
    m = red[0];
    __syncthreads();

    float e0 = __expf(row[tid] - m);
    float e1 = __expf(row[tid + 1024] - m);
    red[tid] = e0 + e1; __syncthreads();
    for (int s = 512; s > 0; s >>= 1) {
        if (tid < s) red[tid] += red[tid + s];
        __syncthreads();
    }
    float inv = 1.0f / red[0];
    row[tid] = e0 * inv;
    row[tid + 1024] = e1 * inv;
}

// ------------------------- K4: context[b,h] = sum_t alpha[b,t]*enc_h[b,t,h]
// 256-t chunks (grid 8 x 32), fp16 enc reads, atomicAdd combine.
__global__ void k4_context(float* __restrict__ out) {
    __shared__ float al[256];
    const int b = blockIdx.y;
    const int t0 = blockIdx.x * 256;
    const int tid = threadIdx.x;
    al[tid] = g_score[(size_t)b * TSEQ + t0 + tid];
    __syncthreads();

    float4 acc = make_float4(0.f, 0.f, 0.f, 0.f);
    const __half* base = g_enc_h + ((size_t)b * TSEQ + t0) * HDIM + tid * 4;
    #pragma unroll 4
    for (int tt = 0; tt < 256; tt++) {
        float a = al[tt];
        uint2 e = *(const uint2*)(base + (size_t)tt * HDIM);
        float2 f01 = __half22float2(*reinterpret_cast<const __half2*>(&e.x));
        float2 f23 = __half22float2(*reinterpret_cast<const __half2*>(&e.y));
        acc.x = fmaf(a, f01.x, acc.x);
        acc.y = fmaf(a, f01.y, acc.y);
        acc.z = fmaf(a, f23.x, acc.z);
        acc.w = fmaf(a, f23.y, acc.w);
    }
    float* o = out + (size_t)b * HDIM + tid * 4;
    atomicAdd(o + 0, acc.x);
    atomicAdd(o + 1, acc.y);
    atomicAdd(o + 2, acc.z);
    atomicAdd(o + 3, acc.w);
}

// ------------------------------------------------------------------- launcher
extern "C" void kernel_launch(void* const* d_in, const int* in_sizes, int n_in,
                              void* d_out, int out_size) {
    const float* enc = (const float*)d_in[0];
    const float* dec = (const float*)d_in[1];
    const float* Wa  = (const float*)d_in[2];
    const float* Ua  = (const float*)d_in[3];
    const float* Va  = (const float*)d_in[4];
    float* out = (float*)d_out;
    (void)in_sizes; (void)n_in; (void)out_size;

    cudaFuncSetAttribute(k2_score, cudaFuncAttributeMaxDynamicSharedMemorySize,
                         SM_TOTAL);

    k0_zero<<<BT / 256, 256>>>(out);
    p_split_enc<<<(BT * HDIM / 4) / 256, 256>>>(enc);
    p_trans_ua<<<dim3(UDIM / 32, HDIM / 32), dim3(32, 8)>>>(Ua);
    k1_decproj<<<dim3(8, 16), 256>>>(dec, Wa);
    k2_score<<<dim3(BT / K2_M, 2), 256, SM_TOTAL>>>(Va);
    k3_softmax<<<BATCH, 1024>>>();
    k4_context<<<dim3(TSEQ / 256, BATCH), 256>>>(out);
}

// round 11
// speedup vs baseline: 8.8657x; 1.0538x over previous
#include <cuda_runtime.h>
#include <cuda_fp16.h>
#include <cstdint>
#include <math.h>

// Bahdanau additive attention, sm_103 base target (no tcgen05).
// R11: k2 single-sync-per-chunk multistage ordering + grid swap for A
// L2 pairing + tanh.approx epilogue; prep kernels fused into one launch.

#define BATCH 32
#define TSEQ  2048
#define HDIM  1024
#define UDIM  1024
#define BT    (BATCH * TSEQ)

// ---------------------------------------------------------------- scratch
__device__ float g_score[BT];
__device__ float g_decproj[BATCH * UDIM];
__device__ __half g_enc_h[(size_t)BT * HDIM];     // 128 MB
__device__ __half g_ua_t[(size_t)UDIM * HDIM];    // transposed [U][H]

// ---------------------------------------------------------------- helpers
__device__ __forceinline__ uint32_t smem_u32(const void* p) {
    uint32_t a;
    asm("{ .reg .u64 t; cvta.to.shared.u64 t, %1; cvt.u32.u64 %0, t; }"
        : "=r"(a) : "l"(p));
    return a;
}
__device__ __forceinline__ uint32_t swz(uint32_t off) {
    return off ^ ((off >> 3) & 0x70);   // SW128 on 128B rows
}
__device__ __forceinline__ void cp16(uint32_t dst, const void* src) {
    asm volatile("cp.async.cg.shared.global [%0], [%1], 16;"
                 :: "r"(dst), "l"(src));
}
#define CP_COMMIT() asm volatile("cp.async.commit_group;" ::: "memory")
#define CP_WAIT1()  asm volatile("cp.async.wait_group 1;" ::: "memory")
#define CP_WAIT0()  asm volatile("cp.async.wait_group 0;" ::: "memory")

__device__ __forceinline__ void ldm4(uint32_t& r0, uint32_t& r1,
                                     uint32_t& r2, uint32_t& r3, uint32_t a) {
    asm volatile("ldmatrix.sync.aligned.m8n8.x4.shared.b16 {%0,%1,%2,%3}, [%4];"
                 : "=r"(r0), "=r"(r1), "=r"(r2), "=r"(r3) : "r"(a));
}
__device__ __forceinline__ void mma16816(float* c, const uint32_t* a,
                                         const uint32_t* b) {
    asm volatile(
        "mma.sync.aligned.m16n8k16.row.col.f32.f16.f16.f32 "
        "{%0,%1,%2,%3}, {%4,%5,%6,%7}, {%8,%9}, {%0,%1,%2,%3};"
        : "+f"(c[0]), "+f"(c[1]), "+f"(c[2]), "+f"(c[3])
        : "r"(a[0]), "r"(a[1]), "r"(a[2]), "r"(a[3]), "r"(b[0]), "r"(b[1]));
}
__device__ __forceinline__ float tanh_fast(float x) {
    float y;
    asm("tanh.approx.f32 %0, %1;" : "=f"(y) : "f"(x));
    return y;
}

// ================================================================ PREP
// One kernel fusing: k1 decproj (128 blocks) | Ua transpose (1024) |
// zero score/out/decproj... careful: decproj must be zero before k1 adds.
// -> k1 accumulates into its own atomics; zero decproj FIRST via ordering
// hazard. Instead: k1 blocks write partials with atomicAdd into g_decproj
// which k0 zeroed -- same kernel = race. Fix: decproj zeroing done by the
// k1 blocks themselves is racy across blocks; instead k1 uses NO zero:
// 16 h-split blocks per u-range atomicAdd; first arrival must see 0.
// Solution: zero g_decproj and g_score in the PREVIOUS launch? No prior
// launch exists. Use a separate tiny zero kernel BEFORE prep for the
// atomic targets (score, decproj, out); bulk split/trans/k1 fused in prep.
#define PB_K1    0
#define PB_TRANS 128
#define PB_SPLIT 1152
#define PREP_BLOCKS (1152 + 32768)

__global__ void k0_zero(float* out) {
    int i = blockIdx.x * blockDim.x + threadIdx.x;   // 0..65535
    g_score[i] = 0.0f;
    if (i < BATCH * HDIM) {
        out[i] = 0.0f;
        g_decproj[i] = 0.0f;
    }
}

__global__ void prep(const float* __restrict__ enc,
                     const float* __restrict__ dec,
                     const float* __restrict__ Wa,
                     const float* __restrict__ Ua) {
    const int bid = blockIdx.x;
    const int tid = threadIdx.x;

    if (bid < PB_TRANS) {
        // ---- k1: dec_proj = dec_hidden @ Wa  (128 blocks)
        __shared__ float dec_s[BATCH][64];
        const int u0 = (bid & 7) * 128;
        const int h0 = (bid >> 3) * 64;
        for (int i = tid; i < BATCH * 64; i += 256) {
            int b = i >> 6, h = i & 63;
            dec_s[b][h] = dec[b * HDIM + h0 + h];
        }
        __syncthreads();
        const int u = u0 + (tid & 127);
        const int hh = (tid >> 7) * 32;
        float acc[BATCH];
        #pragma unroll
        for (int b = 0; b < BATCH; b++) acc[b] = 0.0f;
        #pragma unroll 4
        for (int h = 0; h < 32; h++) {
            float wa = Wa[(size_t)(h0 + hh + h) * UDIM + u];
            #pragma unroll
            for (int b = 0; b < BATCH; b++)
                acc[b] = fmaf(dec_s[b][hh + h], wa, acc[b]);
        }
        #pragma unroll
        for (int b = 0; b < BATCH; b++)
            atomicAdd(&g_decproj[b * UDIM + u], acc[b]);
    } else if (bid < PB_SPLIT) {
        // ---- Ua [H,U] -> transposed [U,H] fp16  (1024 blocks)
        __shared__ float tile[32][33];
        const int rb = bid - PB_TRANS;
        const int u0 = (rb & 31) * 32, h0 = (rb >> 5) * 32;
        const int tx = tid & 31, ty = tid >> 5;   // (32, 8)
        #pragma unroll
        for (int j = 0; j < 4; j++)
            tile[ty + 8 * j][tx] = Ua[(size_t)(h0 + ty + 8 * j) * UDIM + u0 + tx];
        __syncthreads();
        #pragma unroll
        for (int j = 0; j < 4; j++)
            g_ua_t[(size_t)(u0 + ty + 8 * j) * HDIM + h0 + tx] =
                __float2half(tile[tx][ty + 8 * j]);
    } else {
        // ---- enc -> fp16 (32768 blocks, 2 float4 per thread)
        const size_t base = (size_t)(bid - PB_SPLIT) * 512 + tid;
        #pragma unroll
        for (int rep = 0; rep < 2; rep++) {
            size_t i = base + rep * 256;
            float4 v = ((const float4*)enc)[i];
            ushort4 h;
            h.x = __half_as_ushort(__float2half(v.x));
            h.y = __half_as_ushort(__float2half(v.y));
            h.z = __half_as_ushort(__float2half(v.z));
            h.w = __half_as_ushort(__float2half(v.w));
            ((ushort4*)g_enc_h)[i] = h;
        }
    }
}

// ------------------- K2: fused score via fp16 HMMA GEMM + epilogue
// grid (2 u-halves, 512 m-blocks) -- u fast so CTAs sharing A rows are
// co-resident (L2 reuse). 256 threads, occupancy 2, single sync/chunk.
#define K2_M   128
#define K2_N   128
#define K2_KC  64
#define NT_CNT 4                 // N-slabs per CTA (half of U)
#define KT_CNT (HDIM / K2_KC)    // 16
#define IT_TOT (NT_CNT * KT_CNT) // 64
#define N_STG  3

#define TILE_B   (128 * 128)     // [128 rows][64 fp16] = 16 KB
#define OFF_A    0
#define OFF_B    (TILE_B)
#define STAGE_B  (2 * TILE_B)    // 32 KB
#define SM_BIAS  (N_STG * STAGE_B)
#define SM_VA    (SM_BIAS + K2_N * 4)
#define SM_SCORE (SM_VA + K2_N * 4)
#define SM_TOTAL (SM_SCORE + K2_M * 4)   // ~99.8 KB ; 2 CTAs <= 228

__device__ __forceinline__ void issue_chunk(uint32_t sb, int stage, int row0,
                                            int ubase, int it, int tid) {
    const int nt = it >> 4, kt = it & 15;
    const int u0 = ubase + nt * K2_N;
    const int kg = kt * K2_KC;
    const uint32_t base = sb + stage * STAGE_B;
    #pragma unroll
    for (int i = 0; i < 4; i++) {
        int s = tid + i * 256;        // 0..1023
        int r = s >> 3, seg = s & 7;  // row, 16B segment
        uint32_t so = swz((uint32_t)(r * 128 + seg * 16));
        cp16(base + OFF_A + so, g_enc_h + (size_t)(row0 + r) * HDIM + kg + seg * 8);
        cp16(base + OFF_B + so, g_ua_t + (size_t)(u0 + r) * HDIM + kg + seg * 8);
    }
}

__global__ void __launch_bounds__(256, 2)
k2_score(const float* __restrict__ Va) {
    extern __shared__ char smem[];
    const uint32_t sb = smem_u32(smem);
    const int tid = threadIdx.x;
    const int lane = tid & 31;
    const int wid = tid >> 5;
    const int warp_m = wid >> 1;          // 0..3 -> m offset *32
    const int warp_n = wid & 1;           // 0..1 -> n offset *64
    const int row0 = blockIdx.y * K2_M;
    const int ubase = blockIdx.x * (NT_CNT * K2_N);   // 0 or 512
    const int b = row0 / TSEQ;

    float* bias_s  = (float*)(smem + SM_BIAS);
    float* va_s    = (float*)(smem + SM_VA);
    float* score_s = (float*)(smem + SM_SCORE);
    if (tid < K2_M) score_s[tid] = 0.0f;

    // prologue: chunks 0,1 -> stages 0,1
    issue_chunk(sb, 0, row0, ubase, 0, tid);
    CP_COMMIT();
    issue_chunk(sb, 1, row0, ubase, 1, tid);
    CP_COMMIT();

    float c[2][8][4];

    for (int it = 0; it < IT_TOT; it++) {
        const int nt = it >> 4, kt = it & 15;
        const int stage = it % N_STG;

        // wait for chunk `it` (committed groups beyond it: exactly 1
        // except at the tail), then ONE barrier per chunk.
        if (it + 1 < IT_TOT) { CP_WAIT1(); } else { CP_WAIT0(); }
        __syncthreads();

        // issue chunk it+2 into stage (it+2)%3 == (it-1)%3, whose reads
        // all completed before the barrier above.
        if (it + 2 < IT_TOT) {
            issue_chunk(sb, (it + 2) % N_STG, row0, ubase, it + 2, tid);
            CP_COMMIT();
        }

        if (kt == 0) {
            if (tid < K2_N) {
                bias_s[tid] = g_decproj[b * UDIM + ubase + nt * K2_N + tid];
                va_s[tid]   = Va[ubase + nt * K2_N + tid];
            }
            #pragma unroll
            for (int mi = 0; mi < 2; mi++)
                #pragma unroll
                for (int ni = 0; ni < 8; ni++)
                    #pragma unroll
                    for (int q = 0; q < 4; q++)
                        c[mi][ni][q] = 0.0f;
        }

        // ---- compute this chunk (4 x k16 steps)
        const uint32_t aT = sb + stage * STAGE_B + OFF_A;
        const uint32_t bT = sb + stage * STAGE_B + OFF_B;

        #pragma unroll
        for (int ks = 0; ks < 4; ks++) {
            const int kb = ks * 32;  // byte offset of k16 step
            uint32_t ar[2][4];
            #pragma unroll
            for (int mi = 0; mi < 2; mi++) {
                uint32_t rr = warp_m * 32 + mi * 16 + (lane & 15);
                uint32_t off = swz(rr * 128 + kb + (lane >> 4) * 16);
                ldm4(ar[mi][0], ar[mi][1], ar[mi][2], ar[mi][3], aT + off);
            }
            uint32_t br[8][2];
            #pragma unroll
            for (int np = 0; np < 4; np++) {   // each covers 2 n8 tiles
                uint32_t nr = warp_n * 64 + np * 16 + (lane & 7) +
                              ((lane >> 4) ? 8u : 0u);
                uint32_t off = swz(nr * 128 + kb + ((lane >> 3) & 1) * 16);
                uint32_t r0, r1, r2, r3;
                ldm4(r0, r1, r2, r3, bT + off);
                br[np * 2][0] = r0;     br[np * 2][1] = r1;
                br[np * 2 + 1][0] = r2; br[np * 2 + 1][1] = r3;
            }
            #pragma unroll
            for (int mi = 0; mi < 2; mi++)
                #pragma unroll
                for (int ni = 0; ni < 8; ni++)
                    mma16816(c[mi][ni], ar[mi], br[ni]);
        }

        // ---- epilogue at end of each N-slab (bias_s written this slab,
        // protected by the per-chunk barriers in between)
        if (kt == KT_CNT - 1) {
            const int qc = lane & 3;
            const int gl = lane >> 2;
            #pragma unroll
            for (int mi = 0; mi < 2; mi++) {
                float s0 = 0.0f, s1 = 0.0f;  // rows r and r+8
                #pragma unroll
                for (int ni = 0; ni < 8; ni++) {
                    int col = warp_n * 64 + ni * 8 + qc * 2;
                    float b0 = bias_s[col], b1 = bias_s[col + 1];
                    float v0 = va_s[col],  v1 = va_s[col + 1];
                    s0 = fmaf(v0, tanh_fast(c[mi][ni][0] + b0), s0);
                    s0 = fmaf(v1, tanh_fast(c[mi][ni][1] + b1), s0);
                    s1 = fmaf(v0, tanh_fast(c[mi][ni][2] + b0), s1);
                    s1 = fmaf(v1, tanh_fast(c[mi][ni][3] + b1), s1);
                }
                s0 += __shfl_xor_sync(0xFFFFFFFF, s0, 1);
                s0 += __shfl_xor_sync(0xFFFFFFFF, s0, 2);
                s1 += __shfl_xor_sync(0xFFFFFFFF, s1, 1);
                s1 += __shfl_xor_sync(0xFFFFFFFF, s1, 2);
                if (qc == 0) {
                    int r = warp_m * 32 + mi * 16 + gl;
                    atomicAdd(&score_s[r], s0);
                    atomicAdd(&score_s[r + 8], s1);
                }
            }
        }
    }

    __syncthreads();   // score_s complete across warps
    if (tid < K2_M) atomicAdd(&g_score[row0 + tid], score_s[tid]);
}

// ---------------------------------------------- K3: softmax over T (in place)
__global__ void k3_softmax() {
    __shared__ float red[1024];
    const int b = blockIdx.x;
    const int tid = threadIdx.x;
    float* row = g_score + (size_t)b * TSEQ;

    float m = fmaxf(row[tid], row[tid + 1024]);
    red[tid] = m; __syncthreads();
    for (int s = 512; s > 0; s >>= 1) {
        if (tid < s) red[tid] = fmaxf(red[tid], red[tid + s]);
        __syncthreads();
    }
    m = red[0];
    __syncthreads();

    float e0 = __expf(row[tid] - m);
    float e1 = __expf(row[tid + 1024] - m);
    red[tid] = e0 + e1; __syncthreads();
    for (int s = 512; s > 0; s >>= 1) {
        if (tid < s) red[tid] += red[tid + s];
        __syncthreads();
    }
    float inv = 1.0f / red[0];
    row[tid] = e0 * inv;
    row[tid + 1024] = e1 * inv;
}

// ------------------------- K4: context[b,h] = sum_t alpha[b,t]*enc_h[b,t,h]
__global__ void k4_context(float* __restrict__ out) {
    __shared__ float al[256];
    const int b = blockIdx.y;
    const int t0 = blockIdx.x * 256;
    const int tid = threadIdx.x;
    al[tid] = g_score[(size_t)b * TSEQ + t0 + tid];
    __syncthreads();

    float4 acc = make_float4(0.f, 0.f, 0.f, 0.f);
    const __half* base = g_enc_h + ((size_t)b * TSEQ + t0) * HDIM + tid * 4;
    #pragma unroll 4
    for (int tt = 0; tt < 256; tt++) {
        float a = al[tt];
        uint2 e = *(const uint2*)(base + (size_t)tt * HDIM);
        float2 f01 = __half22float2(*reinterpret_cast<const __half2*>(&e.x));
        float2 f23 = __half22float2(*reinterpret_cast<const __half2*>(&e.y));
        acc.x = fmaf(a, f01.x, acc.x);
        acc.y = fmaf(a, f01.y, acc.y);
        acc.z = fmaf(a, f23.x, acc.z);
        acc.w = fmaf(a, f23.y, acc.w);
    }
    float* o = out + (size_t)b * HDIM + tid * 4;
    atomicAdd(o + 0, acc.x);
    atomicAdd(o + 1, acc.y);
    atomicAdd(o + 2, acc.z);
    atomicAdd(o + 3, acc.w);
}

// ------------------------------------------------------------------- launcher
extern "C" void kernel_launch(void* const* d_in, const int* in_sizes, int n_in,
                              void* d_out, int out_size) {
    const float* enc = (const float*)d_in[0];
    const float* dec = (const float*)d_in[1];
    const float* Wa  = (const float*)d_in[2];
    const float* Ua  = (const float*)d_in[3];
    const float* Va  = (const float*)d_in[4];
    float* out = (float*)d_out;
    (void)in_sizes; (void)n_in; (void)out_size;

    cudaFuncSetAttribute(k2_score, cudaFuncAttributeMaxDynamicSharedMemorySize,
                         SM_TOTAL);

    k0_zero<<<BT / 256, 256>>>(out);          // zero atomic targets first
    prep<<<PREP_BLOCKS, 256>>>(enc, dec, Wa, Ua);
    k2_score<<<dim3(2, BT / K2_M), 256, SM_TOTAL>>>(Va);
    k3_softmax<<<BATCH, 1024>>>();
    k4_context<<<dim3(TSEQ / 256, BATCH), 256>>>(out);
}